// round 16
// baseline (speedup 1.0000x reference)
#include <cuda_runtime.h>
#include <cstdint>

#define B_   32
#define T_   128
#define D_   2
#define E_   64
#define L_   64
#define H_   256
#define P_   128
#define BP_  4096

#define SPB_      0.5413248538970947f
#define HALF_L2PI 0.9189385332046727f
#define LOGP_     4.852030263919617f

#define SACT_F 10240                       // 320 rows x 32 p
#define SB_U4  (2 * 3072)                  // main B ring: 2 stages x 3072 uint4 (49KB each)
#define SMEM_BYTES (SACT_F * 4 + SB_U4 * 16)   // 40960 + 98304 = 139264

typedef unsigned long long ull;

// ---------------- persistent device state ----------------
// pre-split fragments: x=bh(k0), y=bl(k0), z=bh(k1), w=bl(k1)
__device__ uint4 g_Bf2[40 * 96 * 32];   // main GEMM (W_ih z-part + W_hh)
__device__ uint4 g_BfE[32 * 16 * 32];   // W_enc [256k][128n]
__device__ uint4 g_BfP[8 * 16 * 32];    // W_pr  [64k][128n]
__device__ float g_Wxy[66 * 768];
__device__ float g_gixy[B_ * 768];
__device__ float g_z[BP_ * L_];
__device__ float g_znew[BP_ * L_];
__device__ float g_hT[BP_ * H_];        // [block(128)][k(256)][p(32)]
__device__ float g_la[BP_];
__device__ float g_lw[BP_];
__device__ float g_lp[B_];
__device__ float g_embed[B_ * T_ * E_];
__device__ unsigned g_keys[T_ * 4];

// ---------------- cp.async ----------------
__device__ __forceinline__ unsigned smem_u32(const void* p) {
    return (unsigned)__cvta_generic_to_shared(p);
}
#define CP_ASYNC16(dst, src) \
    asm volatile("cp.async.ca.shared.global [%0], [%1], 16;" :: "r"(dst), "l"(src))
#define CP_COMMIT() asm volatile("cp.async.commit_group;")
#define CP_WAIT0()  asm volatile("cp.async.wait_group 0;")

// ---------------- tf32 mma ----------------
__device__ __forceinline__ unsigned tf32_hi(float x) {
    unsigned u; asm("cvt.rna.tf32.f32 %0, %1;" : "=r"(u) : "f"(x)); return u;
}
#define MMA_TF32(dp, a0, a1, a2, a3, b0, b1) \
    asm volatile("mma.sync.aligned.m16n8k8.row.col.f32.tf32.tf32.f32 " \
        "{%0,%1,%2,%3}, {%4,%5,%6,%7}, {%8,%9}, {%0,%1,%2,%3};" \
        : "+f"((dp)[0]), "+f"((dp)[1]), "+f"((dp)[2]), "+f"((dp)[3]) \
        : "r"(a0), "r"(a1), "r"(a2), "r"(a3), "r"(b0), "r"(b1))

// ---------------- threefry ----------------
__device__ __forceinline__ void tf2x32(unsigned k0, unsigned k1, unsigned x0, unsigned x1,
                                       unsigned& o0, unsigned& o1) {
    unsigned ks2 = k0 ^ k1 ^ 0x1BD11BDAu;
    x0 += k0; x1 += k1;
#define TF_RND(r) { x0 += x1; x1 = (x1 << (r)) | (x1 >> (32 - (r))); x1 ^= x0; }
    TF_RND(13) TF_RND(15) TF_RND(26) TF_RND(6)   x0 += k1;  x1 += ks2 + 1u;
    TF_RND(17) TF_RND(29) TF_RND(16) TF_RND(24)  x0 += ks2; x1 += k0 + 2u;
    TF_RND(13) TF_RND(15) TF_RND(26) TF_RND(6)   x0 += k0;  x1 += k1 + 3u;
    TF_RND(17) TF_RND(29) TF_RND(16) TF_RND(24)  x0 += k1;  x1 += ks2 + 4u;
    TF_RND(13) TF_RND(15) TF_RND(26) TF_RND(6)   x0 += ks2; x1 += k0 + 5u;
#undef TF_RND
    o0 = x0; o1 = x1;
}
__device__ __forceinline__ unsigned rbits32(unsigned k0, unsigned k1, unsigned i) {
    unsigned o0, o1; tf2x32(k0, k1, 0u, i, o0, o1); return o0 ^ o1;
}
__device__ __forceinline__ float bits_to_u01(unsigned bits) {
    return __uint_as_float((bits >> 9) | 0x3f800000u) - 1.0f;
}
__device__ __forceinline__ float erfinv_x(float x) {
    float w = -log1pf(-x * x);
    float p;
    if (w < 5.0f) {
        w -= 2.5f;
        p = 2.81022636e-08f;
        p = fmaf(p, w, 3.43273939e-07f);
        p = fmaf(p, w, -3.5233877e-06f);
        p = fmaf(p, w, -4.39150654e-06f);
        p = fmaf(p, w, 0.00021858087f);
        p = fmaf(p, w, -0.00125372503f);
        p = fmaf(p, w, -0.00417768164f);
        p = fmaf(p, w, 0.246640727f);
        p = fmaf(p, w, 1.50140941f);
    } else {
        w = sqrtf(w) - 3.0f;
        p = -0.000200214257f;
        p = fmaf(p, w, 0.000100950558f);
        p = fmaf(p, w, 0.00134934322f);
        p = fmaf(p, w, -0.00367342844f);
        p = fmaf(p, w, 0.00573950773f);
        p = fmaf(p, w, -0.0076224613f);
        p = fmaf(p, w, 0.00943887047f);
        p = fmaf(p, w, 1.00167406f);
        p = fmaf(p, w, 2.83297682f);
    }
    return p * x;
}
__device__ __forceinline__ float normal_draw(unsigned k0, unsigned k1, unsigned i) {
    float f = bits_to_u01(rbits32(k0, k1, i));
    const float lo = -0.99999994039535522f;
    float u = fmaxf(lo, fmaf(f, 2.0f, lo));
    return 1.41421356f * erfinv_x(u);
}
__device__ __forceinline__ float gumbel_draw(unsigned k0, unsigned k1, unsigned i) {
    float f = bits_to_u01(rbits32(k0, k1, i));
    const float tiny = 1.17549435e-38f;
    float u = fmaxf(tiny, f + tiny);
    return -logf(-logf(u));
}
__device__ __forceinline__ float softplus_j(float x) {
    return fmaxf(x, 0.0f) + log1pf(expf(-fabsf(x)));
}
__device__ __forceinline__ float nlp(float x, float mu, float sig) {
    float t = (x - mu) / sig;
    return fmaf(-0.5f * t, t, -logf(sig) - HALF_L2PI);
}
__device__ __forceinline__ uint4 split_pair(float b0, float b1) {
    unsigned bh0 = tf32_hi(b0), bh1 = tf32_hi(b1);
    uint4 v;
    v.x = bh0; v.y = __float_as_uint(b0 - __uint_as_float(bh0));
    v.z = bh1; v.w = __float_as_uint(b1 - __uint_as_float(bh1));
    return v;
}

// ---------------- setup ----------------
__global__ void k_setup(const float* __restrict__ x, const float* __restrict__ y,
                        const float* __restrict__ W_emb, const float* __restrict__ b_emb,
                        const float* __restrict__ W_ih, const float* __restrict__ W_hh,
                        const float* __restrict__ W_enc, const float* __restrict__ W_pr,
                        const float* __restrict__ b_ih) {
    if (blockIdx.x == 0 && threadIdx.x == 0) {
        unsigned k0 = 0u, k1 = 42u;
        for (int t = 0; t < T_; ++t) {
            unsigned n0, n1, s0, s1, r0, r1;
            tf2x32(k0, k1, 0u, 0u, n0, n1);
            tf2x32(k0, k1, 0u, 1u, s0, s1);
            tf2x32(k0, k1, 0u, 2u, r0, r1);
            g_keys[t * 4 + 0] = s0; g_keys[t * 4 + 1] = s1;
            g_keys[t * 4 + 2] = r0; g_keys[t * 4 + 3] = r1;
            k0 = n0; k1 = n1;
        }
    }
    const int N1 = BP_ * H_, N2 = BP_ * L_, N3 = BP_, N4 = B_, N5 = B_ * T_ * E_;
    const int N6 = 40 * 96 * 32;
    const int N6E = 32 * 16 * 32;
    const int N6P = 8 * 16 * 32;
    const int N9 = 66 * 768, N10 = B_ * 768;
    const int total = N1 + N2 + N3 + N4 + N5 + N6 + N6E + N6P + N9 + N10;
    int stride = gridDim.x * blockDim.x;
    for (int i = blockIdx.x * blockDim.x + threadIdx.x; i < total; i += stride) {
        int r = i;
        if (r < N1) { g_hT[r] = 0.0f; continue; } r -= N1;
        if (r < N2) { g_z[r] = 0.0f; continue; }  r -= N2;
        if (r < N3) { g_lw[r] = 0.0f; continue; } r -= N3;
        if (r < N4) { g_lp[r] = 0.0f; continue; } r -= N4;
        if (r < N5) {
            int bt = r >> 6, e = r & 63;
            g_embed[r] = fmaf(x[bt * 2], W_emb[e], x[bt * 2 + 1] * W_emb[E_ + e]) + b_emb[e];
            continue;
        } r -= N5;
        if (r < N6) {
            int lane = r & 31, q = r >> 5;
            int vs = q % 96, c = q / 96;
            int gid = lane >> 2, tig = lane & 3;
            int n = vs * 8 + gid;
            int k0 = c * 8 + tig, k1 = k0 + 4;
            float b0 = (k0 < 64) ? W_ih[n * 130 + 64 + k0] : W_hh[n * 256 + k0 - 64];
            float b1 = (k1 < 64) ? W_ih[n * 130 + 64 + k1] : W_hh[n * 256 + k1 - 64];
            g_Bf2[r] = split_pair(b0, b1);
            continue;
        } r -= N6;
        if (r < N6E) {
            int lane = r & 31, q = r >> 5;
            int vs = q & 15, c = q >> 4;
            int gid = lane >> 2, tig = lane & 3;
            int n = vs * 8 + gid;
            int k0 = c * 8 + tig;
            g_BfE[r] = split_pair(W_enc[k0 * 128 + n], W_enc[(k0 + 4) * 128 + n]);
            continue;
        } r -= N6E;
        if (r < N6P) {
            int lane = r & 31, q = r >> 5;
            int vs = q & 15, c = q >> 4;
            int gid = lane >> 2, tig = lane & 3;
            int n = vs * 8 + gid;
            int k0 = c * 8 + tig;
            g_BfP[r] = split_pair(W_pr[k0 * 128 + n], W_pr[(k0 + 4) * 128 + n]);
            continue;
        } r -= N6P;
        if (r < N9) {
            int k = r / 768, j = r % 768;
            int ok = (k < 64) ? k : (64 + k);
            g_Wxy[r] = W_ih[j * 130 + ok]; continue;
        } r -= N9;
        {
            int b = r / 768, j = r % 768;
            float x0 = x[(b * T_) * 2], x1 = x[(b * T_) * 2 + 1];
            float acc = b_ih[j];
            for (int k = 0; k < 64; ++k) {
                float emb = fmaf(x0, W_emb[k], x1 * W_emb[64 + k]) + b_emb[k];
                acc = fmaf(W_ih[j * 130 + k], emb, acc);
            }
            acc = fmaf(W_ih[j * 130 + 128], y[(b * T_) * 2], acc);
            acc = fmaf(W_ih[j * 130 + 129], y[(b * T_) * 2 + 1], acc);
            g_gixy[b * 768 + j] = acc;
        }
    }
}

// A split from s_act row base (krow = rowoff + c*8 + tig), cols acol/acol+8
#define LOAD_A_SPLIT(rowoff, c) \
    int k0_ = (rowoff) + (c) * 8 + tig; \
    float a0f = s_act[k0_ * 32 + acol],       a1f = s_act[k0_ * 32 + acol + 8]; \
    float a2f = s_act[(k0_ + 4) * 32 + acol], a3f = s_act[(k0_ + 4) * 32 + acol + 8]; \
    unsigned ah0 = tf32_hi(a0f), ah1 = tf32_hi(a1f), ah2 = tf32_hi(a2f), ah3 = tf32_hi(a3f); \
    unsigned al0 = __float_as_uint(a0f - __uint_as_float(ah0)); \
    unsigned al1 = __float_as_uint(a1f - __uint_as_float(ah1)); \
    unsigned al2 = __float_as_uint(a2f - __uint_as_float(ah2)); \
    unsigned al3 = __float_as_uint(a3f - __uint_as_float(ah3));

#define MMA3(dp, bb) \
    MMA_TF32(dp, ah0, ah1, ah2, ah3, bb.x, bb.z); \
    MMA_TF32(dp, al0, al1, al2, al3, bb.x, bb.z); \
    MMA_TF32(dp, ah0, ah1, ah2, ah3, bb.y, bb.w);

// ---------------- per-step particle kernel: 32 particles / 512-thread block ----------------
__global__ void __launch_bounds__(512, 1)
k_particle(const float* __restrict__ y, const float* __restrict__ b_hh,
           const float* __restrict__ b_enc, const float* __restrict__ b_pr,
           const float* __restrict__ W_dec, const float* __restrict__ b_dec,
           int t) {
    extern __shared__ float smem_dyn[];
    float* s_act = smem_dyn;                 // [320][32]
    float* s_gi  = smem_dyn + SACT_F;        // exchange [512][35] = 17920 floats (aliases sBm)
    uint4* sBm   = (uint4*)(smem_dyn + SACT_F);   // main B ring, 2 x 3072 uint4
    float* s_enc  = s_gi;                    // overlay after gates: 4096 floats
    float* s_pr   = s_gi + 4096;             // 4096
    float* s_znew = s_gi + 8192;             // 2048
    uint4* sBe   = (uint4*)(s_gi + 10240);   // epi B ring, 2 x 512 uint4 (floats 10240..14336)

    const int bid = blockIdx.x;
    const int b = bid >> 2;
    const int pbase = (bid & 3) << 5;
    const int tid = threadIdx.x;
    const int wnum = tid >> 5, lane = tid & 31;
    const int gid = lane >> 2, tig = lane & 3;
    const int tile = wnum >> 3, wn8 = wnum & 7;
    const int acol = tile * 16 + gid;

    // prefetch main chunk 0 (6 x uint4 per thread, coalesced)
    {
        unsigned d0 = smem_u32(sBm + tid);
        const uint4* g0 = g_Bf2 + tid;
#pragma unroll
        for (int j = 0; j < 6; ++j) CP_ASYNC16(d0 + j * 512 * 16, g0 + j * 512);
        CP_COMMIT();
    }

    for (int i = tid; i < 2048; i += 512) {
        int p = i >> 6, l = i & 63;
        s_act[l * 32 + p] = g_z[(b * P_ + pbase + p) * L_ + l];
    }
    {
        const float4* gh4 = (const float4*)(g_hT + bid * 8192);
        float4* sh4 = (float4*)(s_act + 64 * 32);
        for (int i = tid; i < 2048; i += 512) sh4[i] = gh4[i];
    }
    __syncthreads();

    // dd[0..31]=ru, dd[32..47]=I (c<8), dd[48..63]=H (c>=8)
    float dd[64];
#pragma unroll
    for (int i = 0; i < 64; ++i) dd[i] = 0.0f;

    // ---- pipelined mainloop: B staged through smem ring ----
    for (int c = 0; c < 40; ++c) {
        int buf = c & 1;
        CP_WAIT0();
        __syncthreads();              // stage[buf] visible to all; prior chunk done
        if (c < 39) {
            unsigned d0 = smem_u32(sBm + (buf ^ 1) * 3072 + tid);
            const uint4* g0 = g_Bf2 + (c + 1) * 3072 + tid;
#pragma unroll
            for (int j = 0; j < 6; ++j) CP_ASYNC16(d0 + j * 512 * 16, g0 + j * 512);
            CP_COMMIT();
        }
        const uint4* Bc = sBm + buf * 3072;
        {
            LOAD_A_SPLIT(0, c)
            float* dIH = (c < 8) ? (dd + 32) : (dd + 48);
#pragma unroll
            for (int s = 0; s < 8; ++s) {
                uint4 bb = Bc[(wn8 * 8 + s) * 32 + lane];
                float* dp = dd + s * 4;
                MMA3(dp, bb)
            }
#pragma unroll
            for (int s = 0; s < 4; ++s) {
                uint4 bb = Bc[(64 + wn8 * 4 + s) * 32 + lane];
                float* dp = dIH + s * 4;
                MMA3(dp, bb)
            }
        }
    }
    __syncthreads();   // mainloop done; sBm region reusable as s_gi

    const int t17 = tile * 17;
    // stage 1 exchange: ru
#pragma unroll
    for (int s = 0; s < 8; ++s) {
        int cb = (wn8 * 8 + s) * 8 + 2 * tig;
        s_gi[cb * 35 + t17 + gid] = dd[s * 4 + 0];
        s_gi[(cb + 1) * 35 + t17 + gid] = dd[s * 4 + 1];
        s_gi[cb * 35 + t17 + gid + 8] = dd[s * 4 + 2];
        s_gi[(cb + 1) * 35 + t17 + gid + 8] = dd[s * 4 + 3];
    }
    __syncthreads();
    const int gj = tid & 255, gt = tid >> 8, goff = gt * 17;
    float Rv[16], Uv[16];
#pragma unroll
    for (int p = 0; p < 16; ++p) {
        Rv[p] = s_gi[gj * 35 + goff + p];
        Uv[p] = s_gi[(256 + gj) * 35 + goff + p];
    }
    __syncthreads();
    // stage 2 exchange: I rows 0..255, H rows 256..511
#pragma unroll
    for (int s = 0; s < 4; ++s) {
        int cb = (wn8 * 4 + s) * 8 + 2 * tig;
        s_gi[cb * 35 + t17 + gid] = dd[32 + s * 4 + 0];
        s_gi[(cb + 1) * 35 + t17 + gid] = dd[32 + s * 4 + 1];
        s_gi[cb * 35 + t17 + gid + 8] = dd[32 + s * 4 + 2];
        s_gi[(cb + 1) * 35 + t17 + gid + 8] = dd[32 + s * 4 + 3];
        int ch = 256 + cb;
        s_gi[ch * 35 + t17 + gid] = dd[48 + s * 4 + 0];
        s_gi[(ch + 1) * 35 + t17 + gid] = dd[48 + s * 4 + 1];
        s_gi[ch * 35 + t17 + gid + 8] = dd[48 + s * 4 + 2];
        s_gi[(ch + 1) * 35 + t17 + gid + 8] = dd[48 + s * 4 + 3];
    }
    __syncthreads();

    // ---- GRU gates ----
    {
        float giR = g_gixy[b * 768 + gj] + b_hh[gj];
        float giU = g_gixy[b * 768 + 256 + gj] + b_hh[256 + gj];
        float giI = g_gixy[b * 768 + 512 + gj];
        float bH  = b_hh[512 + gj];
        float4* myrow = (float4*)(s_act + (64 + gj) * 32 + gt * 16);
        float4 hold4[4];
#pragma unroll
        for (int q = 0; q < 4; ++q) hold4[q] = myrow[q];
        float hn[16];
#pragma unroll
        for (int p = 0; p < 16; ++p) {
            float R = Rv[p] + giR;
            float U = Uv[p] + giU;
            float I = s_gi[gj * 35 + goff + p] + giI;
            float Hv = s_gi[(256 + gj) * 35 + goff + p] + bH;
            float r = 1.0f / (1.0f + expf(-R));
            float u = 1.0f / (1.0f + expf(-U));
            float n = tanhf(fmaf(r, Hv, I));
            float hold = ((const float*)hold4)[p];
            hn[p] = fmaf(u, hold, (1.0f - u) * n);
        }
        float4* gout = (float4*)(g_hT + bid * 8192 + gj * 32 + gt * 16);
#pragma unroll
        for (int q = 0; q < 4; ++q) {
            float4 v = make_float4(hn[4 * q], hn[4 * q + 1], hn[4 * q + 2], hn[4 * q + 3]);
            myrow[q] = v;
            gout[q] = v;
        }
    }
    __syncthreads();   // gates done; s_gi free (incl. sBe region)

    // ---- enc + prior via mma, staged B ring ----
    {
        float de[16];
#pragma unroll
        for (int i = 0; i < 16; ++i) de[i] = 0.0f;

        // prefetch epi chunk 0
        {
            unsigned d0 = smem_u32(sBe + tid);
            if (tid < 512) CP_ASYNC16(d0, g_BfE + tid);
            CP_COMMIT();
        }
        for (int cc = 0; cc < 40; ++cc) {
            int buf = cc & 1;
            CP_WAIT0();
            __syncthreads();
            if (cc < 39) {
                const uint4* src = (cc + 1 < 32) ? (g_BfE + (cc + 1) * 512 + tid)
                                                 : (g_BfP + (cc + 1 - 32) * 512 + tid);
                unsigned d0 = smem_u32(sBe + (buf ^ 1) * 512 + tid);
                CP_ASYNC16(d0, src);
                CP_COMMIT();
            }
            const uint4* Bc = sBe + buf * 512;
            if (cc < 32) {
                LOAD_A_SPLIT(64, cc)
#pragma unroll
                for (int s = 0; s < 2; ++s) {
                    uint4 bb = Bc[(wn8 * 2 + s) * 32 + lane];
                    float* dp = de + s * 4;
                    MMA3(dp, bb)
                }
            } else {
                LOAD_A_SPLIT(0, cc - 32)
#pragma unroll
                for (int s = 0; s < 2; ++s) {
                    uint4 bb = Bc[(wn8 * 2 + s) * 32 + lane];
                    float* dp = de + 8 + s * 4;
                    MMA3(dp, bb)
                }
            }
        }
        // write D + bias into s_enc/s_pr [32p][128]
        int row0 = tile * 16 + gid, row1 = row0 + 8;
#pragma unroll
        for (int s = 0; s < 2; ++s) {
            int n0 = (wn8 * 2 + s) * 8 + 2 * tig;
            float be0 = b_enc[n0], be1 = b_enc[n0 + 1];
            s_enc[row0 * 128 + n0]     = de[s * 4 + 0] + be0;
            s_enc[row0 * 128 + n0 + 1] = de[s * 4 + 1] + be1;
            s_enc[row1 * 128 + n0]     = de[s * 4 + 2] + be0;
            s_enc[row1 * 128 + n0 + 1] = de[s * 4 + 3] + be1;
            float bp0 = b_pr[n0], bp1 = b_pr[n0 + 1];
            s_pr[row0 * 128 + n0]     = de[8 + s * 4 + 0] + bp0;
            s_pr[row0 * 128 + n0 + 1] = de[8 + s * 4 + 1] + bp1;
            s_pr[row1 * 128 + n0]     = de[8 + s * 4 + 2] + bp0;
            s_pr[row1 * 128 + n0 + 1] = de[8 + s * 4 + 3] + bp1;
        }
    }
    __syncthreads();

    // ---- sampling + log_alpha: warp w handles particles 2w, 2w+1 ----
    const unsigned ks0 = g_keys[t * 4 + 0], ks1 = g_keys[t * 4 + 1];
    const float y0 = y[(b * T_ + t) * D_ + 0];
    const float y1 = y[(b * T_ + t) * D_ + 1];

    for (int pi = 0; pi < 2; ++pi) {
        int p = wnum * 2 + pi;
        int gp = b * P_ + pbase + p;
        float part = 0.0f;
#pragma unroll
        for (int hh = 0; hh < 2; ++hh) {
            int l = lane + hh * 32;
            float mu_po = s_enc[p * 128 + l];
            float sg_po = softplus_j(s_enc[p * 128 + 64 + l] + SPB_);
            float eps = normal_draw(ks0, ks1, (unsigned)(gp * L_ + l));
            float z = fmaf(sg_po, eps, mu_po);
            s_znew[p * 64 + l] = z;
            g_znew[gp * 64 + l] = z;
            g_z[gp * 64 + l] = z;
            float mu_pr = s_pr[p * 128 + l];
            float sg_pr = softplus_j(s_pr[p * 128 + 64 + l] + SPB_);
            part += nlp(z, mu_pr, sg_pr) - nlp(z, mu_po, sg_po);
        }
#pragma unroll
        for (int off = 16; off; off >>= 1) part += __shfl_down_sync(0xffffffffu, part, off);
        __syncwarp();

        float d0 = 0.f, d1 = 0.f, d2 = 0.f, d3 = 0.f;
#pragma unroll
        for (int hh = 0; hh < 2; ++hh) {
            int l = lane + hh * 32;
            float zv = s_znew[p * 64 + l];
            d0 = fmaf(zv, W_dec[l * 4 + 0], d0);
            d1 = fmaf(zv, W_dec[l * 4 + 1], d1);
            d2 = fmaf(zv, W_dec[l * 4 + 2], d2);
            d3 = fmaf(zv, W_dec[l * 4 + 3], d3);
        }
#pragma unroll
        for (int off = 16; off; off >>= 1) {
            d0 += __shfl_down_sync(0xffffffffu, d0, off);
            d1 += __shfl_down_sync(0xffffffffu, d1, off);
            d2 += __shfl_down_sync(0xffffffffu, d2, off);
            d3 += __shfl_down_sync(0xffffffffu, d3, off);
        }
        if (lane == 0) {
            float la = part;
            float mu0 = d0 + b_dec[0], mu1 = d1 + b_dec[1];
            float sgd0 = softplus_j(d2 + b_dec[2] + SPB_);
            float sgd1 = softplus_j(d3 + b_dec[3] + SPB_);
            la += nlp(y0, mu0, sgd0) + nlp(y1, mu1, sgd1);
            g_la[gp] = la;
        }
    }
}

// ---------------- per-step batch kernel: 4 sub-blocks per batch ----------------
__global__ void __launch_bounds__(256)
k_batch(float* __restrict__ out, const float* __restrict__ y,
        const float* __restrict__ b_ih, int t) {
    __shared__ float s_lw[P_];
    __shared__ float s_emb[66];
    __shared__ float s_r1[4], s_r2[4], s_r3[4], s_r4[4];
    __shared__ float s_flag;

    const int b = blockIdx.x >> 2;
    const int sub = blockIdx.x & 3;
    const int tid = threadIdx.x;
    const int lane = tid & 31, w = tid >> 5;

    if (sub != 0 && t + 1 < T_) {
        if (tid < 64) s_emb[tid] = g_embed[(b * T_ + t + 1) * 64 + tid];
        else if (tid < 66) s_emb[tid] = y[(b * T_ + t + 1) * 2 + (tid - 64)];
    }

    float lpp = 0.0f;
    if (tid < 128) {
        lpp = g_lw[b * P_ + tid] + g_la[b * P_ + tid];
        float m = lpp;
#pragma unroll
        for (int off = 16; off; off >>= 1) m = fmaxf(m, __shfl_xor_sync(0xffffffffu, m, off));
        if (lane == 0) s_r1[w] = m;
    }
    __syncthreads();
    float mx = fmaxf(fmaxf(s_r1[0], s_r1[1]), fmaxf(s_r1[2], s_r1[3]));
    if (tid < 128) {
        float e = expf(lpp - mx);
#pragma unroll
        for (int off = 16; off; off >>= 1) e += __shfl_xor_sync(0xffffffffu, e, off);
        if (lane == 0) s_r2[w] = e;
    }
    __syncthreads();
    float lse = logf(s_r2[0] + s_r2[1] + s_r2[2] + s_r2[3]) + mx;

    float lw = 0.0f;
    if (tid < 128) {
        lw = lpp - lse;
        s_lw[tid] = lw;
        float a = 2.0f * lw;
#pragma unroll
        for (int off = 16; off; off >>= 1) a = fmaxf(a, __shfl_xor_sync(0xffffffffu, a, off));
        if (lane == 0) s_r3[w] = a;
    }
    __syncthreads();
    float m2 = fmaxf(fmaxf(s_r3[0], s_r3[1]), fmaxf(s_r3[2], s_r3[3]));
    if (tid < 128) {
        float e = expf(2.0f * lw - m2);
#pragma unroll
        for (int off = 16; off; off >>= 1) e += __shfl_xor_sync(0xffffffffu, e, off);
        if (lane == 0) s_r4[w] = e;
    }
    __syncthreads();
    if (tid == 0) {
        float log_ess = -(logf(s_r4[0] + s_r4[1] + s_r4[2] + s_r4[3]) + m2);
        s_flag = (expf(log_ess) < 64.0f) ? 1.0f : 0.0f;
        if (sub == 0) {
            float lpn = g_lp[b] + lse;
            g_lp[b] = lpn;
            if (t == T_ - 1) out[b] = lpn;
        }
    }
    __syncthreads();
    bool need = (s_flag != 0.0f);

    if (need) {
        const unsigned kr0 = g_keys[t * 4 + 2], kr1 = g_keys[t * 4 + 3];
        for (int i = 0; i < 4; ++i) {
            int p = sub * 32 + w * 4 + i;
            unsigned base = ((unsigned)p * B_ + (unsigned)b) * P_;
            float bv = -3.4e38f;
            int bj = 0;
#pragma unroll
            for (int jj = 0; jj < 4; ++jj) {
                int j = lane * 4 + jj;
                float v = gumbel_draw(kr0, kr1, base + (unsigned)j) + s_lw[j];
                if (v > bv) { bv = v; bj = j; }
            }
#pragma unroll
            for (int off = 16; off; off >>= 1) {
                float ov = __shfl_xor_sync(0xffffffffu, bv, off);
                int   oj = __shfl_xor_sync(0xffffffffu, bj, off);
                if (ov > bv || (ov == bv && oj < bj)) { bv = ov; bj = oj; }
            }
            if (lane < 16) {
                const float4* src = (const float4*)&g_znew[(b * P_ + bj) * L_];
                float4* dst = (float4*)&g_z[(b * P_ + p) * L_];
                dst[lane] = src[lane];
            }
            if (lane == 0) g_lw[b * P_ + p] = -LOGP_;
        }
    } else {
        if (sub == 0 && tid < 128) g_lw[b * P_ + tid] = lw;
    }

    if (sub != 0 && t + 1 < T_) {
        int j = tid + (sub - 1) * 256;
        float acc = b_ih[j];
        for (int k = 0; k < 64; ++k)
            acc = fmaf(g_Wxy[k * 768 + j], s_emb[k], acc);
        acc = fmaf(g_Wxy[64 * 768 + j], s_emb[64], acc);
        acc = fmaf(g_Wxy[65 * 768 + j], s_emb[65], acc);
        g_gixy[b * 768 + j] = acc;
    }
}

// ---------------- launch ----------------
extern "C" void kernel_launch(void* const* d_in, const int* in_sizes, int n_in,
                              void* d_out, int out_size) {
    const float* x     = (const float*)d_in[0];
    const float* y     = (const float*)d_in[1];
    const float* W_emb = (const float*)d_in[2];
    const float* b_emb = (const float*)d_in[3];
    const float* W_ih  = (const float*)d_in[4];
    const float* W_hh  = (const float*)d_in[5];
    const float* b_ih  = (const float*)d_in[6];
    const float* b_hh  = (const float*)d_in[7];
    const float* W_enc = (const float*)d_in[8];
    const float* b_enc = (const float*)d_in[9];
    const float* W_pr  = (const float*)d_in[10];
    const float* b_pr  = (const float*)d_in[11];
    const float* W_dec = (const float*)d_in[12];
    const float* b_dec = (const float*)d_in[13];
    float* out = (float*)d_out;

    cudaFuncSetAttribute(k_particle, cudaFuncAttributeMaxDynamicSharedMemorySize, SMEM_BYTES);
    k_setup<<<1024, 256>>>(x, y, W_emb, b_emb, W_ih, W_hh, W_enc, W_pr, b_ih);
    for (int t = 0; t < T_; ++t) {
        k_particle<<<BP_ / 32, 512, SMEM_BYTES>>>(y, b_hh, b_enc, b_pr, W_dec, b_dec, t);
        k_batch<<<B_ * 4, 256>>>(out, y, b_ih, t);
    }
}

// round 17
// speedup vs baseline: 2.1523x; 2.1523x over previous
#include <cuda_runtime.h>
#include <cstdint>

#define B_   32
#define T_   128
#define D_   2
#define E_   64
#define L_   64
#define H_   256
#define P_   128
#define BP_  4096

#define SPB_      0.5413248538970947f
#define HALF_L2PI 0.9189385332046727f
#define LOGP_     4.852030263919617f

#define SACT_F 10240           // 320 rows x 32 p
#define SGI_F  17920           // 512 cols x 35
#define SMEM_BYTES ((SACT_F + SGI_F) * 4)

typedef unsigned long long ull;

// ---------------- persistent device state ----------------
// pre-split fragments: x=bh(k0), y=bl(k0), z=bh(k1), w=bl(k1)
__device__ uint4 g_Bf2[40 * 96 * 32];   // main GEMM (W_ih z-part + W_hh)
__device__ uint4 g_BfE[32 * 16 * 32];   // W_enc [256k][128n]
__device__ uint4 g_BfP[8 * 16 * 32];    // W_pr  [64k][128n]
__device__ float g_Wxy[66 * 768];
__device__ float g_gixy[B_ * 768];
__device__ float g_z[BP_ * L_];
__device__ float g_znew[BP_ * L_];
__device__ float g_hT[BP_ * H_];        // [block(128)][k(256)][p(32)]
__device__ float g_la[BP_];
__device__ float g_lw[BP_];
__device__ float g_lp[B_];
__device__ float g_embed[B_ * T_ * E_];
__device__ unsigned g_keys[T_ * 4];

// ---------------- tf32 mma ----------------
__device__ __forceinline__ unsigned tf32_hi(float x) {
    unsigned u; asm("cvt.rna.tf32.f32 %0, %1;" : "=r"(u) : "f"(x)); return u;
}
#define MMA_TF32(dp, a0, a1, a2, a3, b0, b1) \
    asm volatile("mma.sync.aligned.m16n8k8.row.col.f32.tf32.tf32.f32 " \
        "{%0,%1,%2,%3}, {%4,%5,%6,%7}, {%8,%9}, {%0,%1,%2,%3};" \
        : "+f"((dp)[0]), "+f"((dp)[1]), "+f"((dp)[2]), "+f"((dp)[3]) \
        : "r"(a0), "r"(a1), "r"(a2), "r"(a3), "r"(b0), "r"(b1))

// ---------------- threefry ----------------
__device__ __forceinline__ void tf2x32(unsigned k0, unsigned k1, unsigned x0, unsigned x1,
                                       unsigned& o0, unsigned& o1) {
    unsigned ks2 = k0 ^ k1 ^ 0x1BD11BDAu;
    x0 += k0; x1 += k1;
#define TF_RND(r) { x0 += x1; x1 = (x1 << (r)) | (x1 >> (32 - (r))); x1 ^= x0; }
    TF_RND(13) TF_RND(15) TF_RND(26) TF_RND(6)   x0 += k1;  x1 += ks2 + 1u;
    TF_RND(17) TF_RND(29) TF_RND(16) TF_RND(24)  x0 += ks2; x1 += k0 + 2u;
    TF_RND(13) TF_RND(15) TF_RND(26) TF_RND(6)   x0 += k0;  x1 += k1 + 3u;
    TF_RND(17) TF_RND(29) TF_RND(16) TF_RND(24)  x0 += k1;  x1 += ks2 + 4u;
    TF_RND(13) TF_RND(15) TF_RND(26) TF_RND(6)   x0 += ks2; x1 += k0 + 5u;
#undef TF_RND
    o0 = x0; o1 = x1;
}
__device__ __forceinline__ unsigned rbits32(unsigned k0, unsigned k1, unsigned i) {
    unsigned o0, o1; tf2x32(k0, k1, 0u, i, o0, o1); return o0 ^ o1;
}
__device__ __forceinline__ float bits_to_u01(unsigned bits) {
    return __uint_as_float((bits >> 9) | 0x3f800000u) - 1.0f;
}
__device__ __forceinline__ float erfinv_x(float x) {
    float w = -log1pf(-x * x);
    float p;
    if (w < 5.0f) {
        w -= 2.5f;
        p = 2.81022636e-08f;
        p = fmaf(p, w, 3.43273939e-07f);
        p = fmaf(p, w, -3.5233877e-06f);
        p = fmaf(p, w, -4.39150654e-06f);
        p = fmaf(p, w, 0.00021858087f);
        p = fmaf(p, w, -0.00125372503f);
        p = fmaf(p, w, -0.00417768164f);
        p = fmaf(p, w, 0.246640727f);
        p = fmaf(p, w, 1.50140941f);
    } else {
        w = sqrtf(w) - 3.0f;
        p = -0.000200214257f;
        p = fmaf(p, w, 0.000100950558f);
        p = fmaf(p, w, 0.00134934322f);
        p = fmaf(p, w, -0.00367342844f);
        p = fmaf(p, w, 0.00573950773f);
        p = fmaf(p, w, -0.0076224613f);
        p = fmaf(p, w, 0.00943887047f);
        p = fmaf(p, w, 1.00167406f);
        p = fmaf(p, w, 2.83297682f);
    }
    return p * x;
}
__device__ __forceinline__ float normal_draw(unsigned k0, unsigned k1, unsigned i) {
    float f = bits_to_u01(rbits32(k0, k1, i));
    const float lo = -0.99999994039535522f;
    float u = fmaxf(lo, fmaf(f, 2.0f, lo));
    return 1.41421356f * erfinv_x(u);
}
__device__ __forceinline__ float gumbel_draw(unsigned k0, unsigned k1, unsigned i) {
    float f = bits_to_u01(rbits32(k0, k1, i));
    const float tiny = 1.17549435e-38f;
    float u = fmaxf(tiny, f + tiny);
    return -logf(-logf(u));
}
__device__ __forceinline__ float softplus_j(float x) {
    return fmaxf(x, 0.0f) + log1pf(expf(-fabsf(x)));
}
__device__ __forceinline__ float nlp(float x, float mu, float sig) {
    float t = (x - mu) / sig;
    return fmaf(-0.5f * t, t, -logf(sig) - HALF_L2PI);
}
__device__ __forceinline__ uint4 split_pair(float b0, float b1) {
    unsigned bh0 = tf32_hi(b0), bh1 = tf32_hi(b1);
    uint4 v;
    v.x = bh0; v.y = __float_as_uint(b0 - __uint_as_float(bh0));
    v.z = bh1; v.w = __float_as_uint(b1 - __uint_as_float(bh1));
    return v;
}

// ---------------- setup ----------------
__global__ void k_setup(const float* __restrict__ x, const float* __restrict__ y,
                        const float* __restrict__ W_emb, const float* __restrict__ b_emb,
                        const float* __restrict__ W_ih, const float* __restrict__ W_hh,
                        const float* __restrict__ W_enc, const float* __restrict__ W_pr,
                        const float* __restrict__ b_ih) {
    if (blockIdx.x == 0 && threadIdx.x == 0) {
        unsigned k0 = 0u, k1 = 42u;
        for (int t = 0; t < T_; ++t) {
            unsigned n0, n1, s0, s1, r0, r1;
            tf2x32(k0, k1, 0u, 0u, n0, n1);
            tf2x32(k0, k1, 0u, 1u, s0, s1);
            tf2x32(k0, k1, 0u, 2u, r0, r1);
            g_keys[t * 4 + 0] = s0; g_keys[t * 4 + 1] = s1;
            g_keys[t * 4 + 2] = r0; g_keys[t * 4 + 3] = r1;
            k0 = n0; k1 = n1;
        }
    }
    const int N1 = BP_ * H_, N2 = BP_ * L_, N3 = BP_, N4 = B_, N5 = B_ * T_ * E_;
    const int N6 = 40 * 96 * 32;
    const int N6E = 32 * 16 * 32;
    const int N6P = 8 * 16 * 32;
    const int N9 = 66 * 768, N10 = B_ * 768;
    const int total = N1 + N2 + N3 + N4 + N5 + N6 + N6E + N6P + N9 + N10;
    int stride = gridDim.x * blockDim.x;
    for (int i = blockIdx.x * blockDim.x + threadIdx.x; i < total; i += stride) {
        int r = i;
        if (r < N1) { g_hT[r] = 0.0f; continue; } r -= N1;
        if (r < N2) { g_z[r] = 0.0f; continue; }  r -= N2;
        if (r < N3) { g_lw[r] = 0.0f; continue; } r -= N3;
        if (r < N4) { g_lp[r] = 0.0f; continue; } r -= N4;
        if (r < N5) {
            int bt = r >> 6, e = r & 63;
            g_embed[r] = fmaf(x[bt * 2], W_emb[e], x[bt * 2 + 1] * W_emb[E_ + e]) + b_emb[e];
            continue;
        } r -= N5;
        if (r < N6) {
            int lane = r & 31, q = r >> 5;
            int vs = q % 96, c = q / 96;
            int gid = lane >> 2, tig = lane & 3;
            int n = vs * 8 + gid;
            int k0 = c * 8 + tig, k1 = k0 + 4;
            float b0 = (k0 < 64) ? W_ih[n * 130 + 64 + k0] : W_hh[n * 256 + k0 - 64];
            float b1 = (k1 < 64) ? W_ih[n * 130 + 64 + k1] : W_hh[n * 256 + k1 - 64];
            g_Bf2[r] = split_pair(b0, b1);
            continue;
        } r -= N6;
        if (r < N6E) {
            int lane = r & 31, q = r >> 5;
            int vs = q & 15, c = q >> 4;
            int gid = lane >> 2, tig = lane & 3;
            int n = vs * 8 + gid;
            int k0 = c * 8 + tig;
            g_BfE[r] = split_pair(W_enc[k0 * 128 + n], W_enc[(k0 + 4) * 128 + n]);
            continue;
        } r -= N6E;
        if (r < N6P) {
            int lane = r & 31, q = r >> 5;
            int vs = q & 15, c = q >> 4;
            int gid = lane >> 2, tig = lane & 3;
            int n = vs * 8 + gid;
            int k0 = c * 8 + tig;
            g_BfP[r] = split_pair(W_pr[k0 * 128 + n], W_pr[(k0 + 4) * 128 + n]);
            continue;
        } r -= N6P;
        if (r < N9) {
            int k = r / 768, j = r % 768;
            int ok = (k < 64) ? k : (64 + k);
            g_Wxy[r] = W_ih[j * 130 + ok]; continue;
        } r -= N9;
        {
            int b = r / 768, j = r % 768;
            float x0 = x[(b * T_) * 2], x1 = x[(b * T_) * 2 + 1];
            float acc = b_ih[j];
            for (int k = 0; k < 64; ++k) {
                float emb = fmaf(x0, W_emb[k], x1 * W_emb[64 + k]) + b_emb[k];
                acc = fmaf(W_ih[j * 130 + k], emb, acc);
            }
            acc = fmaf(W_ih[j * 130 + 128], y[(b * T_) * 2], acc);
            acc = fmaf(W_ih[j * 130 + 129], y[(b * T_) * 2 + 1], acc);
            g_gixy[b * 768 + j] = acc;
        }
    }
}

// A split from s_act row base (krow = rowoff + c*8 + tig), cols acol/acol+8
#define LOAD_A_SPLIT(rowoff, c) \
    int k0_ = (rowoff) + (c) * 8 + tig; \
    float a0f = s_act[k0_ * 32 + acol],       a1f = s_act[k0_ * 32 + acol + 8]; \
    float a2f = s_act[(k0_ + 4) * 32 + acol], a3f = s_act[(k0_ + 4) * 32 + acol + 8]; \
    unsigned ah0 = tf32_hi(a0f), ah1 = tf32_hi(a1f), ah2 = tf32_hi(a2f), ah3 = tf32_hi(a3f); \
    unsigned al0 = __float_as_uint(a0f - __uint_as_float(ah0)); \
    unsigned al1 = __float_as_uint(a1f - __uint_as_float(ah1)); \
    unsigned al2 = __float_as_uint(a2f - __uint_as_float(ah2)); \
    unsigned al3 = __float_as_uint(a3f - __uint_as_float(ah3));

#define MMA3(dp, bb) \
    MMA_TF32(dp, ah0, ah1, ah2, ah3, bb.x, bb.z); \
    MMA_TF32(dp, al0, al1, al2, al3, bb.x, bb.z); \
    MMA_TF32(dp, ah0, ah1, ah2, ah3, bb.y, bb.w);

// mainloop chunk: 8 ru subtiles + 4 IH subtiles
#define CHUNK(c, dIH) { \
    LOAD_A_SPLIT(0, c) \
    const uint4* Bc = g_Bf2 + (c) * 96 * 32; \
    _Pragma("unroll") \
    for (int s = 0; s < 8; ++s) { \
        uint4 bb = Bc[(wn8 * 8 + s) * 32 + lane]; \
        float* dp = dd + s * 4; \
        MMA3(dp, bb) \
    } \
    _Pragma("unroll") \
    for (int s = 0; s < 4; ++s) { \
        uint4 bb = Bc[(64 + wn8 * 4 + s) * 32 + lane]; \
        float* dp = (dIH) + s * 4; \
        MMA3(dp, bb) \
    } \
}

// ---------------- per-step particle kernel: 32 particles / 512-thread block ----------------
__global__ void __launch_bounds__(512, 1)
k_particle(const float* __restrict__ y, const float* __restrict__ b_hh,
           const float* __restrict__ b_enc, const float* __restrict__ b_pr,
           const float* __restrict__ W_dec, const float* __restrict__ b_dec,
           int t) {
    extern __shared__ float smem_dyn[];
    float* s_act = smem_dyn;            // [320][32]: rows 0..63 z, 64..319 h
    float* s_gi  = smem_dyn + SACT_F;   // [512][35]; overlay after gates:
    float* s_enc  = s_gi;               // 32*128 = 4096
    float* s_pr   = s_gi + 4096;        // 4096
    float* s_znew = s_gi + 8192;        // 2048

    const int bid = blockIdx.x;
    const int b = bid >> 2;
    const int pbase = (bid & 3) << 5;
    const int tid = threadIdx.x;
    const int wnum = tid >> 5, lane = tid & 31;
    const int gid = lane >> 2, tig = lane & 3;
    const int tile = wnum >> 3, wn8 = wnum & 7;
    const int acol = tile * 16 + gid;

    for (int i = tid; i < 2048; i += 512) {
        int p = i >> 6, l = i & 63;
        s_act[l * 32 + p] = g_z[(b * P_ + pbase + p) * L_ + l];
    }
    {
        const float4* gh4 = (const float4*)(g_hT + bid * 8192);
        float4* sh4 = (float4*)(s_act + 64 * 32);
        for (int i = tid; i < 2048; i += 512) sh4[i] = gh4[i];
    }
    __syncthreads();

    // dd[0..31]=ru, dd[32..47]=I (c<8), dd[48..63]=H (c>=8)
    {
        float dd[64];
#pragma unroll
        for (int i = 0; i < 64; ++i) dd[i] = 0.0f;

        for (int c = 0; c < 8; ++c)  { CHUNK(c, dd + 32) }
        for (int c = 8; c < 40; ++c) { CHUNK(c, dd + 48) }

        const int t17 = tile * 17;
        // stage 1 exchange: ru
#pragma unroll
        for (int s = 0; s < 8; ++s) {
            int cb = (wn8 * 8 + s) * 8 + 2 * tig;
            s_gi[cb * 35 + t17 + gid] = dd[s * 4 + 0];
            s_gi[(cb + 1) * 35 + t17 + gid] = dd[s * 4 + 1];
            s_gi[cb * 35 + t17 + gid + 8] = dd[s * 4 + 2];
            s_gi[(cb + 1) * 35 + t17 + gid + 8] = dd[s * 4 + 3];
        }
        __syncthreads();
        const int gj = tid & 255, gt = tid >> 8, goff = gt * 17;
        float Rv[16], Uv[16];
#pragma unroll
        for (int p = 0; p < 16; ++p) {
            Rv[p] = s_gi[gj * 35 + goff + p];
            Uv[p] = s_gi[(256 + gj) * 35 + goff + p];
        }
        __syncthreads();
        // stage 2 exchange: I rows 0..255, H rows 256..511
#pragma unroll
        for (int s = 0; s < 4; ++s) {
            int cb = (wn8 * 4 + s) * 8 + 2 * tig;
            s_gi[cb * 35 + t17 + gid] = dd[32 + s * 4 + 0];
            s_gi[(cb + 1) * 35 + t17 + gid] = dd[32 + s * 4 + 1];
            s_gi[cb * 35 + t17 + gid + 8] = dd[32 + s * 4 + 2];
            s_gi[(cb + 1) * 35 + t17 + gid + 8] = dd[32 + s * 4 + 3];
            int ch = 256 + cb;
            s_gi[ch * 35 + t17 + gid] = dd[48 + s * 4 + 0];
            s_gi[(ch + 1) * 35 + t17 + gid] = dd[48 + s * 4 + 1];
            s_gi[ch * 35 + t17 + gid + 8] = dd[48 + s * 4 + 2];
            s_gi[(ch + 1) * 35 + t17 + gid + 8] = dd[48 + s * 4 + 3];
        }
        __syncthreads();

        // GRU gates: thread (j=gj, tile=gt)
        float giR = g_gixy[b * 768 + gj] + b_hh[gj];
        float giU = g_gixy[b * 768 + 256 + gj] + b_hh[256 + gj];
        float giI = g_gixy[b * 768 + 512 + gj];
        float bH  = b_hh[512 + gj];
        float4* myrow = (float4*)(s_act + (64 + gj) * 32 + gt * 16);
        float4 hold4[4];
#pragma unroll
        for (int q = 0; q < 4; ++q) hold4[q] = myrow[q];
        float hn[16];
#pragma unroll
        for (int p = 0; p < 16; ++p) {
            float R = Rv[p] + giR;
            float U = Uv[p] + giU;
            float I = s_gi[gj * 35 + goff + p] + giI;
            float Hv = s_gi[(256 + gj) * 35 + goff + p] + bH;
            float r = 1.0f / (1.0f + expf(-R));
            float u = 1.0f / (1.0f + expf(-U));
            float n = tanhf(fmaf(r, Hv, I));
            float hold = ((const float*)hold4)[p];
            hn[p] = fmaf(u, hold, (1.0f - u) * n);
        }
        float4* gout = (float4*)(g_hT + bid * 8192 + gj * 32 + gt * 16);
#pragma unroll
        for (int q = 0; q < 4; ++q) {
            float4 v = make_float4(hn[4 * q], hn[4 * q + 1], hn[4 * q + 2], hn[4 * q + 3]);
            myrow[q] = v;
            gout[q] = v;
        }
    }
    __syncthreads();   // h_new visible; s_gi free for overlay

    // ---- enc + prior via mma: warp does 2 enc subtiles + 2 pr subtiles ----
    {
        float de[16];   // [0..7]=enc subtiles s0,s1; [8..15]=pr subtiles s0,s1
#pragma unroll
        for (int i = 0; i < 16; ++i) de[i] = 0.0f;

#pragma unroll 2
        for (int c = 0; c < 32; ++c) {       // enc over h_new (rows 64..319)
            LOAD_A_SPLIT(64, c)
#pragma unroll
            for (int s = 0; s < 2; ++s) {
                uint4 bb = g_BfE[((c * 16) + (wn8 * 2 + s)) * 32 + lane];
                float* dp = de + s * 4;
                MMA3(dp, bb)
            }
        }
#pragma unroll 2
        for (int c = 0; c < 8; ++c) {        // prior over z (rows 0..63)
            LOAD_A_SPLIT(0, c)
#pragma unroll
            for (int s = 0; s < 2; ++s) {
                uint4 bb = g_BfP[((c * 16) + (wn8 * 2 + s)) * 32 + lane];
                float* dp = de + 8 + s * 4;
                MMA3(dp, bb)
            }
        }
        // write D + bias into s_enc/s_pr [32p][128]
        int row0 = tile * 16 + gid, row1 = row0 + 8;
#pragma unroll
        for (int s = 0; s < 2; ++s) {
            int n0 = (wn8 * 2 + s) * 8 + 2 * tig;
            float be0 = b_enc[n0], be1 = b_enc[n0 + 1];
            s_enc[row0 * 128 + n0]     = de[s * 4 + 0] + be0;
            s_enc[row0 * 128 + n0 + 1] = de[s * 4 + 1] + be1;
            s_enc[row1 * 128 + n0]     = de[s * 4 + 2] + be0;
            s_enc[row1 * 128 + n0 + 1] = de[s * 4 + 3] + be1;
            float bp0 = b_pr[n0], bp1 = b_pr[n0 + 1];
            s_pr[row0 * 128 + n0]     = de[8 + s * 4 + 0] + bp0;
            s_pr[row0 * 128 + n0 + 1] = de[8 + s * 4 + 1] + bp1;
            s_pr[row1 * 128 + n0]     = de[8 + s * 4 + 2] + bp0;
            s_pr[row1 * 128 + n0 + 1] = de[8 + s * 4 + 3] + bp1;
        }
    }
    __syncthreads();

    // ---- sampling + log_alpha: warp w handles particles 2w, 2w+1 ----
    const unsigned ks0 = g_keys[t * 4 + 0], ks1 = g_keys[t * 4 + 1];
    const float y0 = y[(b * T_ + t) * D_ + 0];
    const float y1 = y[(b * T_ + t) * D_ + 1];

    for (int pi = 0; pi < 2; ++pi) {
        int p = wnum * 2 + pi;
        int gp = b * P_ + pbase + p;
        float part = 0.0f;
#pragma unroll
        for (int hh = 0; hh < 2; ++hh) {
            int l = lane + hh * 32;
            float mu_po = s_enc[p * 128 + l];
            float sg_po = softplus_j(s_enc[p * 128 + 64 + l] + SPB_);
            float eps = normal_draw(ks0, ks1, (unsigned)(gp * L_ + l));
            float z = fmaf(sg_po, eps, mu_po);
            s_znew[p * 64 + l] = z;
            g_znew[gp * 64 + l] = z;
            g_z[gp * 64 + l] = z;
            float mu_pr = s_pr[p * 128 + l];
            float sg_pr = softplus_j(s_pr[p * 128 + 64 + l] + SPB_);
            part += nlp(z, mu_pr, sg_pr) - nlp(z, mu_po, sg_po);
        }
#pragma unroll
        for (int off = 16; off; off >>= 1) part += __shfl_down_sync(0xffffffffu, part, off);
        __syncwarp();

        float d0 = 0.f, d1 = 0.f, d2 = 0.f, d3 = 0.f;
#pragma unroll
        for (int hh = 0; hh < 2; ++hh) {
            int l = lane + hh * 32;
            float zv = s_znew[p * 64 + l];
            d0 = fmaf(zv, W_dec[l * 4 + 0], d0);
            d1 = fmaf(zv, W_dec[l * 4 + 1], d1);
            d2 = fmaf(zv, W_dec[l * 4 + 2], d2);
            d3 = fmaf(zv, W_dec[l * 4 + 3], d3);
        }
#pragma unroll
        for (int off = 16; off; off >>= 1) {
            d0 += __shfl_down_sync(0xffffffffu, d0, off);
            d1 += __shfl_down_sync(0xffffffffu, d1, off);
            d2 += __shfl_down_sync(0xffffffffu, d2, off);
            d3 += __shfl_down_sync(0xffffffffu, d3, off);
        }
        if (lane == 0) {
            float la = part;
            float mu0 = d0 + b_dec[0], mu1 = d1 + b_dec[1];
            float sgd0 = softplus_j(d2 + b_dec[2] + SPB_);
            float sgd1 = softplus_j(d3 + b_dec[3] + SPB_);
            la += nlp(y0, mu0, sgd0) + nlp(y1, mu1, sgd1);
            g_la[gp] = la;
        }
    }
}

// ---------------- per-step batch kernel: 4 sub-blocks per batch ----------------
__global__ void __launch_bounds__(256)
k_batch(float* __restrict__ out, const float* __restrict__ y,
        const float* __restrict__ b_ih, int t) {
    __shared__ float s_lw[P_];
    __shared__ float s_emb[66];
    __shared__ float s_r1[4], s_r2[4], s_r3[4], s_r4[4];
    __shared__ float s_flag;

    const int b = blockIdx.x >> 2;
    const int sub = blockIdx.x & 3;
    const int tid = threadIdx.x;
    const int lane = tid & 31, w = tid >> 5;

    if (sub != 0 && t + 1 < T_) {
        if (tid < 64) s_emb[tid] = g_embed[(b * T_ + t + 1) * 64 + tid];
        else if (tid < 66) s_emb[tid] = y[(b * T_ + t + 1) * 2 + (tid - 64)];
    }

    float lpp = 0.0f;
    if (tid < 128) {
        lpp = g_lw[b * P_ + tid] + g_la[b * P_ + tid];
        float m = lpp;
#pragma unroll
        for (int off = 16; off; off >>= 1) m = fmaxf(m, __shfl_xor_sync(0xffffffffu, m, off));
        if (lane == 0) s_r1[w] = m;
    }
    __syncthreads();
    float mx = fmaxf(fmaxf(s_r1[0], s_r1[1]), fmaxf(s_r1[2], s_r1[3]));
    if (tid < 128) {
        float e = expf(lpp - mx);
#pragma unroll
        for (int off = 16; off; off >>= 1) e += __shfl_xor_sync(0xffffffffu, e, off);
        if (lane == 0) s_r2[w] = e;
    }
    __syncthreads();
    float lse = logf(s_r2[0] + s_r2[1] + s_r2[2] + s_r2[3]) + mx;

    float lw = 0.0f;
    if (tid < 128) {
        lw = lpp - lse;
        s_lw[tid] = lw;
        float a = 2.0f * lw;
#pragma unroll
        for (int off = 16; off; off >>= 1) a = fmaxf(a, __shfl_xor_sync(0xffffffffu, a, off));
        if (lane == 0) s_r3[w] = a;
    }
    __syncthreads();
    float m2 = fmaxf(fmaxf(s_r3[0], s_r3[1]), fmaxf(s_r3[2], s_r3[3]));
    if (tid < 128) {
        float e = expf(2.0f * lw - m2);
#pragma unroll
        for (int off = 16; off; off >>= 1) e += __shfl_xor_sync(0xffffffffu, e, off);
        if (lane == 0) s_r4[w] = e;
    }
    __syncthreads();
    if (tid == 0) {
        float log_ess = -(logf(s_r4[0] + s_r4[1] + s_r4[2] + s_r4[3]) + m2);
        s_flag = (expf(log_ess) < 64.0f) ? 1.0f : 0.0f;
        if (sub == 0) {
            float lpn = g_lp[b] + lse;
            g_lp[b] = lpn;
            if (t == T_ - 1) out[b] = lpn;
        }
    }
    __syncthreads();
    bool need = (s_flag != 0.0f);

    if (need) {
        const unsigned kr0 = g_keys[t * 4 + 2], kr1 = g_keys[t * 4 + 3];
        for (int i = 0; i < 4; ++i) {
            int p = sub * 32 + w * 4 + i;
            unsigned base = ((unsigned)p * B_ + (unsigned)b) * P_;
            float bv = -3.4e38f;
            int bj = 0;
#pragma unroll
            for (int jj = 0; jj < 4; ++jj) {
                int j = lane * 4 + jj;
                float v = gumbel_draw(kr0, kr1, base + (unsigned)j) + s_lw[j];
                if (v > bv) { bv = v; bj = j; }
            }
#pragma unroll
            for (int off = 16; off; off >>= 1) {
                float ov = __shfl_xor_sync(0xffffffffu, bv, off);
                int   oj = __shfl_xor_sync(0xffffffffu, bj, off);
                if (ov > bv || (ov == bv && oj < bj)) { bv = ov; bj = oj; }
            }
            if (lane < 16) {
                const float4* src = (const float4*)&g_znew[(b * P_ + bj) * L_];
                float4* dst = (float4*)&g_z[(b * P_ + p) * L_];
                dst[lane] = src[lane];
            }
            if (lane == 0) g_lw[b * P_ + p] = -LOGP_;
        }
    } else {
        if (sub == 0 && tid < 128) g_lw[b * P_ + tid] = lw;
    }

    if (sub != 0 && t + 1 < T_) {
        int j = tid + (sub - 1) * 256;
        float acc = b_ih[j];
        for (int k = 0; k < 64; ++k)
            acc = fmaf(g_Wxy[k * 768 + j], s_emb[k], acc);
        acc = fmaf(g_Wxy[64 * 768 + j], s_emb[64], acc);
        acc = fmaf(g_Wxy[65 * 768 + j], s_emb[65], acc);
        g_gixy[b * 768 + j] = acc;
    }
}

// ---------------- launch ----------------
extern "C" void kernel_launch(void* const* d_in, const int* in_sizes, int n_in,
                              void* d_out, int out_size) {
    const float* x     = (const float*)d_in[0];
    const float* y     = (const float*)d_in[1];
    const float* W_emb = (const float*)d_in[2];
    const float* b_emb = (const float*)d_in[3];
    const float* W_ih  = (const float*)d_in[4];
    const float* W_hh  = (const float*)d_in[5];
    const float* b_ih  = (const float*)d_in[6];
    const float* b_hh  = (const float*)d_in[7];
    const float* W_enc = (const float*)d_in[8];
    const float* b_enc = (const float*)d_in[9];
    const float* W_pr  = (const float*)d_in[10];
    const float* b_pr  = (const float*)d_in[11];
    const float* W_dec = (const float*)d_in[12];
    const float* b_dec = (const float*)d_in[13];
    float* out = (float*)d_out;

    cudaFuncSetAttribute(k_particle, cudaFuncAttributeMaxDynamicSharedMemorySize, SMEM_BYTES);
    k_setup<<<1024, 256>>>(x, y, W_emb, b_emb, W_ih, W_hh, W_enc, W_pr, b_ih);
    for (int t = 0; t < T_; ++t) {
        k_particle<<<BP_ / 32, 512, SMEM_BYTES>>>(y, b_hh, b_enc, b_pr, W_dec, b_dec, t);
        k_batch<<<B_ * 4, 256>>>(out, y, b_ih, t);
    }
}